// round 1
// baseline (speedup 1.0000x reference)
#include <cuda_runtime.h>

// Problem constants
#define Bn 8
#define Cc 16
#define Hh 128
#define Ww 128
#define PLANE (Bn*Cc*Hh*Ww)   // 2,097,152 floats per [B,C,H,W] stream

// Ping-pong stream buffers: [parity][row][stream(right,up,down)][B*C*H*W]
__device__ float g_buf[2u*4u*3u*(unsigned)PLANE];

// One wavefront cell: y = relu(conv3x3(concat(in0,in1,in2), Wc) + bc); split into R/U/D.
// Null input slot == zeros == skip that 16-channel chunk entirely.
// Block: 16x16 spatial tile of one batch image. 256 threads:
//   thread = cog(4 out-channel groups of 12) x 64 pixel-slots (2x2 px each).
// Accumulators packed as f32x2 over out-channel pairs -> fma.rn.f32x2.
__global__ __launch_bounds__(256, 2) void cell_kernel(
    const float* __restrict__ in0, const float* __restrict__ in1, const float* __restrict__ in2,
    const float* __restrict__ Wc, const float* __restrict__ bc,
    float* __restrict__ outR, float* __restrict__ outU, float* __restrict__ outD)
{
    __shared__ __align__(16) float s_in[16 * 324];      // 16 ch x 18x18 halo tile (20.25 KB)
    __shared__ __align__(16) float s_w[16 * 9 * 48];    // [ci][k][co] (27 KB)

    const int tid = threadIdx.x;
    const int cog = tid & 3;          // out-channel group 0..3 (12 co each)
    const int ps  = tid >> 2;         // pixel slot 0..63
    const int pby = ps >> 3, pbx = ps & 7;
    const int py0 = pby * 2, px0 = pbx * 2;     // 2x2 pixel block origin in tile
    const int gx0 = blockIdx.x * 16, gy0 = blockIdx.y * 16;
    const int bz  = blockIdx.z;
    const int cobase = cog * 12;

    unsigned long long acc[6][2][2];
    #pragma unroll
    for (int j = 0; j < 6; j++)
        #pragma unroll
        for (int py = 0; py < 2; py++)
            #pragma unroll
            for (int px = 0; px < 2; px++)
                acc[j][py][px] = 0ull;

    const float* srcs[3] = {in0, in1, in2};

    for (int chunk = 0; chunk < 3; chunk++) {
        const float* src = srcs[chunk];
        if (!src) continue;   // zero slot: contributes nothing (uniform branch)

        // ---- cooperative load: input tile (16 ch x 18 x 18, zero-padded SAME halo) ----
        for (int e = tid; e < 16 * 324; e += 256) {
            int ci = e / 324; int r = e - ci * 324;
            int ty = r / 18;  int tx = r - ty * 18;
            int gy = gy0 - 1 + ty, gx = gx0 - 1 + tx;
            float v = 0.f;
            if ((unsigned)gy < 128u && (unsigned)gx < 128u)
                v = src[((bz * 16 + ci) * 128 + gy) * 128 + gx];
            s_in[e] = v;
        }
        // ---- cooperative load: weights, transposed to [ci][k][co] so co is contiguous ----
        for (int e = tid; e < 48 * 144; e += 256) {
            int co = e / 144; int r = e - co * 144;
            int ci = r / 9;   int k  = r - ci * 9;
            s_w[(ci * 9 + k) * 48 + co] = Wc[(co * 48 + chunk * 16 + ci) * 9 + k];
        }
        __syncthreads();

        // ---- compute: 16 input channels ----
        #pragma unroll 4
        for (int ci = 0; ci < 16; ci++) {
            // 4x4 input patch for this thread's 2x2 pixel block, broadcast-packed
            unsigned long long xp[16];
            const float* base = &s_in[ci * 324 + py0 * 18 + px0];
            #pragma unroll
            for (int dy = 0; dy < 4; dy++)
                #pragma unroll
                for (int dx = 0; dx < 4; dx++) {
                    float v = base[dy * 18 + dx];
                    asm("mov.b64 %0, {%1, %1};" : "=l"(xp[dy * 4 + dx]) : "f"(v));
                }
            #pragma unroll
            for (int k = 0; k < 9; k++) {
                const int ky = k / 3, kx = k - ky * 3;
                const unsigned long long* wrow =
                    reinterpret_cast<const unsigned long long*>(&s_w[(ci * 9 + k) * 48 + cobase]);
                #pragma unroll
                for (int jp = 0; jp < 6; jp++) {
                    unsigned long long w = wrow[jp];   // weight pair (co, co+1): one LDS.64
                    #pragma unroll
                    for (int py = 0; py < 2; py++)
                        #pragma unroll
                        for (int px = 0; px < 2; px++)
                            asm("fma.rn.f32x2 %0, %1, %2, %0;"
                                : "+l"(acc[jp][py][px])
                                : "l"(w), "l"(xp[(py + ky) * 4 + (px + kx)]));
                }
            }
        }
        __syncthreads();
    }

    // ---- epilogue: bias + relu, split into right/up/down streams ----
    float* outs[3] = {outR, outU, outD};
    #pragma unroll
    for (int jp = 0; jp < 6; jp++) {
        int co0 = cobase + jp * 2;   // even; pair never straddles a stream boundary
        float b0 = bc[co0], b1 = bc[co0 + 1];
        int s0 = co0 >> 4, ch0 = co0 & 15;
        #pragma unroll
        for (int py = 0; py < 2; py++)
            #pragma unroll
            for (int px = 0; px < 2; px++) {
                float lo, hi;
                asm("mov.b64 {%0, %1}, %2;" : "=f"(lo), "=f"(hi) : "l"(acc[jp][py][px]));
                lo = fmaxf(lo + b0, 0.f);
                hi = fmaxf(hi + b1, 0.f);
                int gy = gy0 + py0 + py, gx = gx0 + px0 + px;
                float* o = outs[s0];
                o[((bz * 16 + ch0)     * 128 + gy) * 128 + gx] = lo;
                o[((bz * 16 + ch0 + 1) * 128 + gy) * 128 + gx] = hi;
            }
    }
}

extern "C" void kernel_launch(void* const* d_in, const int* in_sizes, int n_in,
                              void* d_out, int out_size)
{
    const float* x = (const float*)d_in[0];            // [8,16,128,128]
    const float* W = (const float*)d_in[1];            // [4,4,48,48,3,3]
    const float* b = (const float*)d_in[2];            // [4,4,48]
    float* out = (float*)d_out;                        // [8,16,128,128]

    float* buf = nullptr;
    cudaGetSymbolAddress((void**)&buf, g_buf);
    auto BUF = [&](int par, int row, int st) {
        return buf + (((size_t)par * 4 + row) * 3 + st) * (size_t)PLANE;
    };

    dim3 grid(8, 8, 8);   // (W tiles, H tiles, batch)
    dim3 block(256);

    // Wavefront: columns left->right, rows top->bottom (matches reference order).
    for (int col = 0; col < 4; col++) {
        int p = col & 1, q = p ^ 1;
        for (int row = 0; row < 4; row++) {
            const float *i0, *i1 = nullptr, *i2 = nullptr;
            if (col == 0) {
                i0 = (row == 0) ? x : BUF(p, row - 1, 2);         // down from above (this col)
            } else {
                i0 = BUF(q, row, 0);                              // right from prev col
                if (row == 0)       i1 = BUF(q, row + 1, 1);      // up from below (prev col)
                else if (row == 3)  i1 = BUF(p, row - 1, 2);      // down from above (this col)
                else {              i1 = BUF(q, row + 1, 1);
                                    i2 = BUF(p, row - 1, 2); }
            }
            float* oR = BUF(p, row, 0);
            float* oU = BUF(p, row, 1);
            float* oD = BUF(p, row, 2);
            if (col == 3 && row == 3) oR = out;   // final result = right stream of cell (3,3)

            const float* Wc = W + (size_t)(col * 4 + row) * 48 * 48 * 9;
            const float* bc = b + (size_t)(col * 4 + row) * 48;
            cell_kernel<<<grid, block>>>(i0, i1, i2, Wc, bc, oR, oU, oD);
        }
    }
}

// round 2
// speedup vs baseline: 1.0037x; 1.0037x over previous
#include <cuda_runtime.h>

// Problem constants
#define Bn 8
#define Cc 16
#define Hh 128
#define Ww 128
#define PLANE (Bn*Cc*Hh*Ww)   // 2,097,152 floats per [B,C,H,W] stream

// Ping-pong stream buffers: [parity][row][stream(right,up,down)][B*C*H*W]
__device__ float g_buf[2u*4u*3u*(unsigned)PLANE];

// One wavefront cell: y = relu(conv3x3(concat(in0,in1,in2), Wc) + bc); split into R/U/D.
// Null input slot == zeros == skip that 16-channel chunk entirely.
// Block: 16x16 spatial tile of one batch image. 256 threads:
//   thread = cog(4 out-channel groups of 12) x 64 pixel-slots (2x2 px each).
// Accumulators packed as f32x2 over out-channel pairs -> fma.rn.f32x2.
__global__ __launch_bounds__(256, 2) void cell_kernel(
    const float* __restrict__ in0, const float* __restrict__ in1, const float* __restrict__ in2,
    const float* __restrict__ Wc, const float* __restrict__ bc,
    float* __restrict__ outR, float* __restrict__ outU, float* __restrict__ outD)
{
    __shared__ __align__(16) float s_in[16 * 324];      // 16 ch x 18x18 halo tile (20.25 KB)
    __shared__ __align__(16) float s_w[16 * 9 * 48];    // [ci][k][co] (27 KB)

    const int tid = threadIdx.x;
    const int cog = tid & 3;          // out-channel group 0..3 (12 co each)
    const int ps  = tid >> 2;         // pixel slot 0..63
    const int pby = ps >> 3, pbx = ps & 7;
    const int py0 = pby * 2, px0 = pbx * 2;     // 2x2 pixel block origin in tile
    const int gx0 = blockIdx.x * 16, gy0 = blockIdx.y * 16;
    const int bz  = blockIdx.z;
    const int cobase = cog * 12;

    unsigned long long acc[6][2][2];
    #pragma unroll
    for (int j = 0; j < 6; j++)
        #pragma unroll
        for (int py = 0; py < 2; py++)
            #pragma unroll
            for (int px = 0; px < 2; px++)
                acc[j][py][px] = 0ull;

    const float* srcs[3] = {in0, in1, in2};

    for (int chunk = 0; chunk < 3; chunk++) {
        const float* src = srcs[chunk];
        if (!src) continue;   // zero slot: contributes nothing (uniform branch)

        // ---- cooperative load: input tile (16 ch x 18 x 18, zero-padded SAME halo) ----
        for (int e = tid; e < 16 * 324; e += 256) {
            int ci = e / 324; int r = e - ci * 324;
            int ty = r / 18;  int tx = r - ty * 18;
            int gy = gy0 - 1 + ty, gx = gx0 - 1 + tx;
            float v = 0.f;
            if ((unsigned)gy < 128u && (unsigned)gx < 128u)
                v = src[((bz * 16 + ci) * 128 + gy) * 128 + gx];
            s_in[e] = v;
        }
        // ---- cooperative load: weights, transposed to [ci][k][co] so co is contiguous ----
        for (int e = tid; e < 48 * 144; e += 256) {
            int co = e / 144; int r = e - co * 144;
            int ci = r / 9;   int k  = r - ci * 9;
            s_w[(ci * 9 + k) * 48 + co] = Wc[(co * 48 + chunk * 16 + ci) * 9 + k];
        }
        __syncthreads();

        // ---- compute: 16 input channels ----
        #pragma unroll 4
        for (int ci = 0; ci < 16; ci++) {
            // 4x4 input patch for this thread's 2x2 pixel block, broadcast-packed
            unsigned long long xp[16];
            const float* base = &s_in[ci * 324 + py0 * 18 + px0];
            #pragma unroll
            for (int dy = 0; dy < 4; dy++)
                #pragma unroll
                for (int dx = 0; dx < 4; dx++) {
                    float v = base[dy * 18 + dx];
                    asm("mov.b64 %0, {%1, %1};" : "=l"(xp[dy * 4 + dx]) : "f"(v));
                }
            #pragma unroll
            for (int k = 0; k < 9; k++) {
                const int ky = k / 3, kx = k - ky * 3;
                const unsigned long long* wrow =
                    reinterpret_cast<const unsigned long long*>(&s_w[(ci * 9 + k) * 48 + cobase]);
                #pragma unroll
                for (int jp = 0; jp < 6; jp++) {
                    unsigned long long w = wrow[jp];   // weight pair (co, co+1): one LDS.64
                    #pragma unroll
                    for (int py = 0; py < 2; py++)
                        #pragma unroll
                        for (int px = 0; px < 2; px++)
                            asm("fma.rn.f32x2 %0, %1, %2, %0;"
                                : "+l"(acc[jp][py][px])
                                : "l"(w), "l"(xp[(py + ky) * 4 + (px + kx)]));
                }
            }
        }
        __syncthreads();
    }

    // ---- epilogue: bias + relu, split into right/up/down streams ----
    float* outs[3] = {outR, outU, outD};
    #pragma unroll
    for (int jp = 0; jp < 6; jp++) {
        int co0 = cobase + jp * 2;   // even; pair never straddles a stream boundary
        float b0 = bc[co0], b1 = bc[co0 + 1];
        int s0 = co0 >> 4, ch0 = co0 & 15;
        #pragma unroll
        for (int py = 0; py < 2; py++)
            #pragma unroll
            for (int px = 0; px < 2; px++) {
                float lo, hi;
                asm("mov.b64 {%0, %1}, %2;" : "=f"(lo), "=f"(hi) : "l"(acc[jp][py][px]));
                lo = fmaxf(lo + b0, 0.f);
                hi = fmaxf(hi + b1, 0.f);
                int gy = gy0 + py0 + py, gx = gx0 + px0 + px;
                float* o = outs[s0];
                o[((bz * 16 + ch0)     * 128 + gy) * 128 + gx] = lo;
                o[((bz * 16 + ch0 + 1) * 128 + gy) * 128 + gx] = hi;
            }
    }
}

extern "C" void kernel_launch(void* const* d_in, const int* in_sizes, int n_in,
                              void* d_out, int out_size)
{
    const float* x = (const float*)d_in[0];            // [8,16,128,128]
    const float* W = (const float*)d_in[1];            // [4,4,48,48,3,3]
    const float* b = (const float*)d_in[2];            // [4,4,48]
    float* out = (float*)d_out;                        // [8,16,128,128]

    float* buf = nullptr;
    cudaGetSymbolAddress((void**)&buf, g_buf);
    auto BUF = [&](int par, int row, int st) {
        return buf + (((size_t)par * 4 + row) * 3 + st) * (size_t)PLANE;
    };

    dim3 grid(8, 8, 8);   // (W tiles, H tiles, batch)
    dim3 block(256);

    // Wavefront: columns left->right, rows top->bottom (matches reference order).
    for (int col = 0; col < 4; col++) {
        int p = col & 1, q = p ^ 1;
        for (int row = 0; row < 4; row++) {
            const float *i0, *i1 = nullptr, *i2 = nullptr;
            if (col == 0) {
                i0 = (row == 0) ? x : BUF(p, row - 1, 2);         // down from above (this col)
            } else {
                i0 = BUF(q, row, 0);                              // right from prev col
                if (row == 0)       i1 = BUF(q, row + 1, 1);      // up from below (prev col)
                else if (row == 3)  i1 = BUF(p, row - 1, 2);      // down from above (this col)
                else {              i1 = BUF(q, row + 1, 1);
                                    i2 = BUF(p, row - 1, 2); }
            }
            float* oR = BUF(p, row, 0);
            float* oU = BUF(p, row, 1);
            float* oD = BUF(p, row, 2);
            if (col == 3 && row == 3) oR = out;   // final result = right stream of cell (3,3)

            const float* Wc = W + (size_t)(col * 4 + row) * 48 * 48 * 9;
            const float* bc = b + (size_t)(col * 4 + row) * 48;
            cell_kernel<<<grid, block>>>(i0, i1, i2, Wc, bc, oR, oU, oD);
        }
    }
}